// round 1
// baseline (speedup 1.0000x reference)
#include <cuda_runtime.h>
#include <math.h>

#define BATCH  2
#define SEQ    2048
#define DIM    1024
#define VOCAB  32000
#define NLAYER 6
#define MROWS  (BATCH*SEQ)   // 4096

// ---------------- scratch (static device globals; no allocations) ----------------
__device__ float g_xA[BATCH*SEQ*DIM];   // activations ping
__device__ float g_xB[BATCH*SEQ*DIM];   // activations pong
__device__ float g_c [BATCH*DIM*SEQ];   // LN'd, transposed (B,D,S); also reused as final normalized x
__device__ float g_y [BATCH*DIM*SEQ];   // conv/silu output, (B,D,S)
__device__ float g_rf[MROWS*DIM];       // refined pre-gate
__device__ float g_gp[MROWS*DIM];       // gate pre-activation
__device__ float g_mu[MROWS];
__device__ float g_rs[MROWS];

// ---------------- helpers ----------------
__device__ __forceinline__ float warpRed(float v) {
    #pragma unroll
    for (int o = 16; o; o >>= 1) v += __shfl_xor_sync(0xffffffffu, v, o);
    return v;
}

// ---------------- embed + sinusoidal PE ----------------
__global__ void k_embed(const int* __restrict__ ids, const float* __restrict__ emb,
                        float* __restrict__ x) {
    int idx = blockIdx.x * 256 + threadIdx.x;          // over B*S*D
    int d   = idx & (DIM - 1);
    int row = idx >> 10;                               // b*S + s
    int s   = row & (SEQ - 1);
    int tok = ids[row];
    // freq for pair j uses exponent 2j * (-ln(10000)/D)
    float ang = (float)s * expf((float)(d & ~1) * (-9.210340371976184f / (float)DIM));
    float pe  = (d & 1) ? cosf(ang) : sinf(ang);
    x[idx] = emb[(size_t)tok * DIM + d] + pe;
}

// ---------------- per-row layernorm stats ----------------
__global__ void __launch_bounds__(256) k_lnstats(const float* __restrict__ x,
                                                 float* __restrict__ mu, float* __restrict__ rs) {
    int row = blockIdx.x;
    int t   = threadIdx.x;
    const float* p = x + (size_t)row * DIM;
    float v[4];
    float s = 0.f;
    #pragma unroll
    for (int i = 0; i < 4; i++) { v[i] = p[t + i * 256]; s += v[i]; }
    __shared__ float red[8];
    __shared__ float sh_m;
    s = warpRed(s);
    if ((t & 31) == 0) red[t >> 5] = s;
    __syncthreads();
    if (t == 0) {
        float tot = 0.f;
        #pragma unroll
        for (int i = 0; i < 8; i++) tot += red[i];
        sh_m = tot / (float)DIM;
    }
    __syncthreads();
    float m = sh_m;
    float q = 0.f;
    #pragma unroll
    for (int i = 0; i < 4; i++) { float dd = v[i] - m; q += dd * dd; }
    q = warpRed(q);
    if ((t & 31) == 0) red[t >> 5] = q;
    __syncthreads();
    if (t == 0) {
        float tot = 0.f;
        #pragma unroll
        for (int i = 0; i < 8; i++) tot += red[i];
        mu[row] = m;
        rs[row] = rsqrtf(tot / (float)DIM + 1e-5f);
    }
}

// ---------------- fused normalize + transpose (B,S,D)->(B,D,S) ----------------
__global__ void k_tn(const float* __restrict__ x, const float* __restrict__ mu,
                     const float* __restrict__ rs, const float* __restrict__ gg,
                     const float* __restrict__ bb, float* __restrict__ c) {
    __shared__ float tile[32][33];
    int b  = blockIdx.z;
    int s0 = blockIdx.x * 32;
    int d0 = blockIdx.y * 32;
    int tx = threadIdx.x, ty = threadIdx.y;   // 32x8
    #pragma unroll
    for (int i = 0; i < 4; i++) {
        int s = s0 + ty + i * 8;
        int r = b * SEQ + s;
        tile[ty + i * 8][tx] = (x[(size_t)r * DIM + d0 + tx] - mu[r]) * rs[r];
    }
    __syncthreads();
    #pragma unroll
    for (int i = 0; i < 4; i++) {
        int d = d0 + ty + i * 8;
        c[((size_t)(b * DIM + d)) * SEQ + s0 + tx] = tile[tx][ty + i * 8] * gg[d] + bb[d];
    }
}

// ---------------- conv chain: conv3 -> conv64 (+res) -> conv64 -> mix -> silu ----------------
__global__ void __launch_bounds__(256) k_conv(const float* __restrict__ cbuf,
                                              const float* __restrict__ local_w,
                                              const float* __restrict__ filt_w,
                                              const float* __restrict__ mix_w,
                                              float* __restrict__ ybuf, int layer) {
    int bd = blockIdx.x;               // b*DIM + d
    int d  = bd & (DIM - 1);
    __shared__ float s_in[SEQ + 64];   // 32-pad each side (zeros = conv padding)
    __shared__ float s_t [SEQ + 64];
    __shared__ float w3[4], w0[64], w1[64], smix[1];
    int t = threadIdx.x;
    if (t < 3)                  w3[t]       = local_w[((size_t)layer * DIM + d) * 3 + t];
    if (t >= 64 && t < 128)     w0[t - 64]  = filt_w[(((size_t)layer * 2 + 0) * DIM + d) * 64 + (t - 64)];
    if (t >= 128 && t < 192)    w1[t - 128] = filt_w[(((size_t)layer * 2 + 1) * DIM + d) * 64 + (t - 128)];
    if (t == 224)               smix[0]     = mix_w[layer * DIM + d];
    if (t < 32) { s_in[t] = 0.f; s_t[t] = 0.f; s_in[SEQ + 32 + t] = 0.f; s_t[SEQ + 32 + t] = 0.f; }
    const float* cp = cbuf + (size_t)bd * SEQ;
    #pragma unroll
    for (int i = 0; i < 8; i++) s_in[32 + t + i * 256] = cp[t + i * 256];
    __syncthreads();
    // conv3, pad (1,1): out[t] = sum_k in[t-1+k]*w3[k]
    #pragma unroll
    for (int i = 0; i < 8; i++) {
        int tt = 32 + t + i * 256;
        s_t[tt] = s_in[tt - 1] * w3[0] + s_in[tt] * w3[1] + s_in[tt + 1] * w3[2];
    }
    __syncthreads();
    // conv64 #1 over s_t, pad (32,31), + residual of s_in; result overwrites s_in (own index only)
    float r[8];
    #pragma unroll
    for (int i = 0; i < 8; i++) r[i] = s_in[32 + t + i * 256];
    #pragma unroll
    for (int k = 0; k < 64; k++) {
        float wv = w0[k];
        #pragma unroll
        for (int i = 0; i < 8; i++) r[i] += wv * s_t[t + i * 256 + k];   // (32+tt)-32+k
    }
    #pragma unroll
    for (int i = 0; i < 8; i++) s_in[32 + t + i * 256] = r[i];
    __syncthreads();
    // conv64 #2 over s_in, then per-channel mix + silu
    float mix = smix[0];
    #pragma unroll
    for (int i = 0; i < 8; i++) r[i] = 0.f;
    #pragma unroll
    for (int k = 0; k < 64; k++) {
        float wv = w1[k];
        #pragma unroll
        for (int i = 0; i < 8; i++) r[i] += wv * s_in[t + i * 256 + k];
    }
    float* yp = ybuf + (size_t)bd * SEQ;
    #pragma unroll
    for (int i = 0; i < 8; i++) {
        float m = r[i] * mix;
        yp[t + i * 256] = m / (1.f + expf(-m));   // silu
    }
}

// ---------------- generic fp32 SIMT GEMM: C[M,N] = A(MxK) * B(KxN) + bias ----------------
// AT: A stored (B,D,S) i.e. A[m,k] = A[(m/SEQ)*DIM*SEQ + k*SEQ + (m%SEQ)]
// BT: B stored row-major (N,K), i.e. B[k,n] = Bm[n*K + k]
template <bool AT, bool BT, bool BIAS>
__global__ void __launch_bounds__(256) k_gemm(const float* __restrict__ A,
                                              const float* __restrict__ Bm,
                                              const float* __restrict__ bias,
                                              float* __restrict__ C, int N, int K) {
    __shared__ float As[8][128];
    __shared__ float Bs[8][128];
    int tid = threadIdx.x;
    int m0 = blockIdx.y * 128, n0 = blockIdx.x * 128;
    int row = (tid / 16) * 8, col = (tid % 16) * 8;
    float acc[8][8];
    #pragma unroll
    for (int i = 0; i < 8; i++)
        #pragma unroll
        for (int j = 0; j < 8; j++) acc[i][j] = 0.f;

    for (int k0 = 0; k0 < K; k0 += 8) {
        if (AT) {
            int k = tid >> 5, m4 = (tid & 31) * 4;
            int m = m0 + m4;
            float4 v = *(const float4*)(A + (size_t)(m >> 11) * DIM * SEQ
                                          + (size_t)(k0 + k) * SEQ + (m & (SEQ - 1)));
            *(float4*)&As[k][m4] = v;
        } else {
            int m = tid >> 1, kq = (tid & 1) * 4;
            float4 v = *(const float4*)(A + (size_t)(m0 + m) * K + k0 + kq);
            As[kq + 0][m] = v.x; As[kq + 1][m] = v.y; As[kq + 2][m] = v.z; As[kq + 3][m] = v.w;
        }
        if (BT) {
            int n = tid >> 1, kq = (tid & 1) * 4;
            float4 v = *(const float4*)(Bm + (size_t)(n0 + n) * K + k0 + kq);
            Bs[kq + 0][n] = v.x; Bs[kq + 1][n] = v.y; Bs[kq + 2][n] = v.z; Bs[kq + 3][n] = v.w;
        } else {
            int k = tid >> 5, n4 = (tid & 31) * 4;
            float4 v = *(const float4*)(Bm + (size_t)(k0 + k) * N + n0 + n4);
            *(float4*)&Bs[k][n4] = v;
        }
        __syncthreads();
        #pragma unroll
        for (int k = 0; k < 8; k++) {
            float a[8], b[8];
            *(float4*)&a[0] = *(const float4*)&As[k][row];
            *(float4*)&a[4] = *(const float4*)&As[k][row + 4];
            *(float4*)&b[0] = *(const float4*)&Bs[k][col];
            *(float4*)&b[4] = *(const float4*)&Bs[k][col + 4];
            #pragma unroll
            for (int i = 0; i < 8; i++)
                #pragma unroll
                for (int j = 0; j < 8; j++) acc[i][j] += a[i] * b[j];
        }
        __syncthreads();
    }

    float bv[8];
    #pragma unroll
    for (int j = 0; j < 8; j++) bv[j] = BIAS ? bias[n0 + col + j] : 0.f;
    #pragma unroll
    for (int i = 0; i < 8; i++) {
        float4 o0, o1;
        o0.x = acc[i][0] + bv[0]; o0.y = acc[i][1] + bv[1];
        o0.z = acc[i][2] + bv[2]; o0.w = acc[i][3] + bv[3];
        o1.x = acc[i][4] + bv[4]; o1.y = acc[i][5] + bv[5];
        o1.z = acc[i][6] + bv[6]; o1.w = acc[i][7] + bv[7];
        size_t off = (size_t)(m0 + row + i) * N + n0 + col;
        *(float4*)(C + off)     = o0;
        *(float4*)(C + off + 4) = o1;
    }
}

// ---------------- gate combine ----------------
__global__ void k_combine(const float* __restrict__ rf, const float* __restrict__ gp,
                          const float* __restrict__ orig, float* __restrict__ xo) {
    int idx = blockIdx.x * 256 + threadIdx.x;
    float gate = 1.f / (1.f + expf(-gp[idx]));
    xo[idx] = gate * rf[idx] + (1.f - gate) * orig[idx];
}

// ---------------- row-wise normalize (final LN, keeps (B,S,D)) ----------------
__global__ void k_norm_rows(const float* __restrict__ x, const float* __restrict__ mu,
                            const float* __restrict__ rs, const float* __restrict__ gg,
                            const float* __restrict__ bb, float* __restrict__ o) {
    int idx = blockIdx.x * 256 + threadIdx.x;
    int d = idx & (DIM - 1);
    int row = idx >> 10;
    o[idx] = (x[idx] - mu[row]) * rs[row] * gg[d] + bb[d];
}

// ---------------- launch ----------------
extern "C" void kernel_launch(void* const* d_in, const int* in_sizes, int n_in,
                              void* d_out, int out_size) {
    const int*   ids     = (const int*)  d_in[0];
    const float* emb     = (const float*)d_in[1];
    const float* local_w = (const float*)d_in[2];
    const float* filt_w  = (const float*)d_in[3];
    const float* mix_w   = (const float*)d_in[4];
    const float* ln1_g   = (const float*)d_in[5];
    const float* ln1_b   = (const float*)d_in[6];
    const float* ref_W   = (const float*)d_in[7];
    const float* ref_b   = (const float*)d_in[8];
    const float* gate_W  = (const float*)d_in[9];
    const float* gate_b  = (const float*)d_in[10];
    const float* lnf_g   = (const float*)d_in[11];
    const float* lnf_b   = (const float*)d_in[12];
    const float* out_W   = (const float*)d_in[13];
    const float* out_b   = (const float*)d_in[14];
    float* out = (float*)d_out;

    float *xA, *xB, *cb, *yb, *rb, *gb, *mub, *rsb;
    cudaGetSymbolAddress((void**)&xA,  g_xA);
    cudaGetSymbolAddress((void**)&xB,  g_xB);
    cudaGetSymbolAddress((void**)&cb,  g_c);
    cudaGetSymbolAddress((void**)&yb,  g_y);
    cudaGetSymbolAddress((void**)&rb,  g_rf);
    cudaGetSymbolAddress((void**)&gb,  g_gp);
    cudaGetSymbolAddress((void**)&mub, g_mu);
    cudaGetSymbolAddress((void**)&rsb, g_rs);

    k_embed<<<BATCH * SEQ * DIM / 256, 256>>>(ids, emb, xA);

    float* cur = xA;
    float* nxt = xB;
    for (int l = 0; l < NLAYER; l++) {
        k_lnstats<<<MROWS, 256>>>(cur, mub, rsb);
        k_tn<<<dim3(SEQ / 32, DIM / 32, BATCH), dim3(32, 8)>>>(cur, mub, rsb,
                                                               ln1_g + l * DIM, ln1_b + l * DIM, cb);
        k_conv<<<BATCH * DIM, 256>>>(cb, local_w, filt_w, mix_w, yb, l);
        k_gemm<true,  true, true><<<dim3(DIM / 128, MROWS / 128), 256>>>(
            yb,  ref_W  + (size_t)l * DIM * DIM, ref_b  + l * DIM, rb, DIM, DIM);
        k_gemm<false, true, true><<<dim3(DIM / 128, MROWS / 128), 256>>>(
            cur, gate_W + (size_t)l * DIM * DIM, gate_b + l * DIM, gb, DIM, DIM);
        k_combine<<<MROWS * DIM / 256, 256>>>(rb, gb, cur, nxt);
        float* tmp = cur; cur = nxt; nxt = tmp;
    }

    k_lnstats<<<MROWS, 256>>>(cur, mub, rsb);
    k_norm_rows<<<MROWS * DIM / 256, 256>>>(cur, mub, rsb, lnf_g, lnf_b, cb);
    k_gemm<false, false, true><<<dim3(VOCAB / 128, MROWS / 128), 256>>>(
        cb, out_W, out_b, out, VOCAB, DIM);
}